// round 2
// baseline (speedup 1.0000x reference)
#include <cuda_runtime.h>

#define N_NODES   8192
#define B_BATCH   2
#define D_IN      64
#define D_OUT     32
#define K_ITERS   4
#define C_CH      (K_ITERS * D_OUT)   // 128
#define ALPHA_F   0.1f
#define OMA_F     0.9f                 // 1 - alpha
#define BN_EPS_F  1e-5f
#define MAX_NNZ   128                  // mean nnz/row ~42, >10 sigma margin
#define NSAMP     (B_BATCH * N_NODES)  // 16384
#define SPMM_BLOCKS 256                // 32 rows per block

// ---------------- device scratch ----------------
__device__ float g_h  [B_BATCH * N_NODES * D_OUT];   // x @ W
__device__ float g_h0 [B_BATCH * N_NODES * D_OUT];   // alpha * (x0 @ W0)
__device__ int2  g_cv [(size_t)N_NODES * MAX_NNZ];   // {col, bitcast(val*(1-a))}
__device__ int   g_cnt[N_NODES];                     // padded count (mult of 8)
__device__ float g_y  [(size_t)B_BATCH * N_NODES * C_CH];
__device__ float g_psum[K_ITERS * SPMM_BLOCKS * D_OUT];
__device__ float g_psq [K_ITERS * SPMM_BLOCKS * D_OUT];
__device__ float g_scale[C_CH];
__device__ float g_shift[C_CH];

// ---------------- 1) input projections ----------------
__global__ void gemm_kernel(const float* __restrict__ x,
                            const float* __restrict__ x0,
                            const float* __restrict__ W,
                            const float* __restrict__ W0) {
    __shared__ float Ws [D_IN * D_OUT];
    __shared__ float W0s[D_IN * D_OUT];
    __shared__ float xs [8][D_IN];
    __shared__ float x0s[8][D_IN];

    const int t = threadIdx.x;
    const int rowBase = blockIdx.x * 8;

    for (int i = t; i < D_IN * D_OUT; i += 256) { Ws[i] = W[i]; W0s[i] = W0[i]; }
    for (int i = t; i < 8 * D_IN; i += 256) {
        int r = rowBase + (i >> 6);
        int d = i & 63;
        xs [i >> 6][d] = x [(size_t)r * D_IN + d];
        x0s[i >> 6][d] = x0[(size_t)r * D_IN + d];
    }
    __syncthreads();

    const int rr = t >> 5;
    const int f  = t & 31;
    const int row = rowBase + rr;
    float acc = 0.f, acc0 = 0.f;
#pragma unroll
    for (int d = 0; d < D_IN; ++d) {
        acc  = fmaf(xs [rr][d], Ws [d * D_OUT + f], acc);
        acc0 = fmaf(x0s[rr][d], W0s[d * D_OUT + f], acc0);
    }
    g_h [(size_t)row * D_OUT + f] = acc;
    g_h0[(size_t)row * D_OUT + f] = acc0 * ALPHA_F;
}

// ---------------- 2) dense -> padded packed CSR ----------------
__global__ void csr_kernel(const float* __restrict__ adj) {
    const int warp = (blockIdx.x * blockDim.x + threadIdx.x) >> 5;
    const int lane = threadIdx.x & 31;
    if (warp >= N_NODES) return;

    const float4* row = (const float4*)(adj + (size_t)warp * N_NODES);
    const int out = warp * MAX_NNZ;
    int base = 0;

#pragma unroll 2
    for (int ch = 0; ch < N_NODES / 128; ++ch) {
        float4 v = __ldcs(&row[ch * 32 + lane]);   // streaming: don't pollute L2
        float e[4] = {v.x, v.y, v.z, v.w};
#pragma unroll
        for (int k = 0; k < 4; ++k) {
            const bool nz = (e[k] != 0.0f);
            const unsigned m = __ballot_sync(0xffffffffu, nz);
            if (nz) {
                int pos = base + __popc(m & ((1u << lane) - 1u));
                if (pos < MAX_NNZ)
                    g_cv[out + pos] = make_int2(ch * 128 + lane * 4 + k,
                                                __float_as_int(e[k] * OMA_F));
            }
            base += __popc(m);
        }
    }
    int cnt  = base < MAX_NNZ ? base : MAX_NNZ;
    int cntp = (cnt + 7) & ~7;
    if (cntp > MAX_NNZ) cntp = MAX_NNZ;
    for (int j = cnt + lane; j < cntp; j += 32)
        g_cv[out + j] = make_int2(0, 0);           // val=0 padding
    if (lane == 0) g_cnt[warp] = cntp;
}

// ---------------- 3) SpMM iterate + fused BN partials ----------------
// dst slice kslice of g_y = (1-a)*adj@src + a*h0
__global__ void __launch_bounds__(1024) spmm_kernel(const float* __restrict__ src,
                                                    int sstride, int kslice) {
    __shared__ float shs[32][32];
    __shared__ float shq[32][32];

    const int warp = threadIdx.x >> 5;
    const int lane = threadIdx.x & 31;
    const int r    = blockIdx.x * 32 + warp;

    const int2* __restrict__ cv = g_cv + (size_t)r * MAX_NNZ;
    const int cntp = g_cnt[r];

    float acc0 = g_h0[(size_t)r * D_OUT + lane];
    float acc1 = g_h0[(size_t)(N_NODES + r) * D_OUT + lane];

    const float* __restrict__ s0 = src;
    const float* __restrict__ s1 = src + (size_t)N_NODES * sstride;

    for (int j = 0; j < cntp; j += 8) {
#pragma unroll
        for (int t = 0; t < 8; ++t) {
            const int2 p = __ldg(&cv[j + t]);       // lane-uniform 8B load
            const float vv = __int_as_float(p.y);
            acc0 = fmaf(vv, __ldg(&s0[(size_t)p.x * sstride + lane]), acc0);
            acc1 = fmaf(vv, __ldg(&s1[(size_t)p.x * sstride + lane]), acc1);
        }
    }

    g_y[(size_t)r * C_CH + kslice * D_OUT + lane]             = acc0;
    g_y[(size_t)(N_NODES + r) * C_CH + kslice * D_OUT + lane] = acc1;

    // fused BN partials over this block's 32 rows x 2 batches
    shs[warp][lane] = acc0 + acc1;
    shq[warp][lane] = fmaf(acc0, acc0, acc1 * acc1);
    __syncthreads();
    if (warp == 0) {
        float s = 0.f;
#pragma unroll
        for (int w = 0; w < 32; ++w) s += shs[w][lane];
        g_psum[(kslice * SPMM_BLOCKS + blockIdx.x) * D_OUT + lane] = s;
    }
    if (warp == 1) {
        float q = 0.f;
#pragma unroll
        for (int w = 0; w < 32; ++w) q += shq[w][lane];
        g_psq[(kslice * SPMM_BLOCKS + blockIdx.x) * D_OUT + lane] = q;
    }
}

// ---------------- 4) finalize BN params ----------------
__global__ void bn_final_kernel(const float* __restrict__ gamma,
                                const float* __restrict__ beta) {
    __shared__ float ss[256], qq[256];
    const int c = threadIdx.x & 127;
    const int h = threadIdx.x >> 7;
    const int slice = c >> 5, lane = c & 31;

    float s = 0.f, q = 0.f;
    for (int b = h; b < SPMM_BLOCKS; b += 2) {
        s += g_psum[(slice * SPMM_BLOCKS + b) * D_OUT + lane];
        q += g_psq [(slice * SPMM_BLOCKS + b) * D_OUT + lane];
    }
    ss[threadIdx.x] = s;
    qq[threadIdx.x] = q;
    __syncthreads();
    if (h == 0) {
        s = ss[c] + ss[c + 128];
        q = qq[c] + qq[c + 128];
        const float inv  = 1.0f / (float)NSAMP;
        const float mean = s * inv;
        const float var  = q * inv - mean * mean;
        const float sc   = gamma[c] * rsqrtf(var + BN_EPS_F);
        g_scale[c] = sc;
        g_shift[c] = beta[c] - mean * sc;
    }
}

// ---------------- 5) normalize + ReLU ----------------
__global__ void norm_kernel(float* __restrict__ out) {
    const int idx = blockIdx.x * blockDim.x + threadIdx.x;   // float4 index
    float4 v = ((const float4*)g_y)[idx];
    const int c0 = (idx & 31) * 4;
    v.x = fmaxf(0.f, fmaf(v.x, g_scale[c0 + 0], g_shift[c0 + 0]));
    v.y = fmaxf(0.f, fmaf(v.y, g_scale[c0 + 1], g_shift[c0 + 1]));
    v.z = fmaxf(0.f, fmaf(v.z, g_scale[c0 + 2], g_shift[c0 + 2]));
    v.w = fmaxf(0.f, fmaf(v.w, g_scale[c0 + 3], g_shift[c0 + 3]));
    ((float4*)out)[idx] = v;
}

// ---------------- launch ----------------
extern "C" void kernel_launch(void* const* d_in, const int* in_sizes, int n_in,
                              void* d_out, int out_size) {
    const float* x     = (const float*)d_in[0];
    const float* x0    = (const float*)d_in[1];
    const float* adj   = (const float*)d_in[2];
    const float* W     = (const float*)d_in[3];
    const float* W0    = (const float*)d_in[4];
    const float* gamma = (const float*)d_in[5];
    const float* beta  = (const float*)d_in[6];
    float* out = (float*)d_out;

    float *h, *y;
    cudaGetSymbolAddress((void**)&h, g_h);
    cudaGetSymbolAddress((void**)&y, g_y);

    gemm_kernel<<<(B_BATCH * N_NODES) / 8, 256>>>(x, x0, W, W0);
    csr_kernel<<<N_NODES / 8, 256>>>(adj);

    // 4 propagation iterates; iterate k>=1 reads slice k-1 of g_y in place
    spmm_kernel<<<SPMM_BLOCKS, 1024>>>(h,              D_OUT, 0);
    spmm_kernel<<<SPMM_BLOCKS, 1024>>>(y + 0 * D_OUT,  C_CH,  1);
    spmm_kernel<<<SPMM_BLOCKS, 1024>>>(y + 1 * D_OUT,  C_CH,  2);
    spmm_kernel<<<SPMM_BLOCKS, 1024>>>(y + 2 * D_OUT,  C_CH,  3);

    bn_final_kernel<<<1, 256>>>(gamma, beta);
    norm_kernel<<<(NSAMP * C_CH / 4) / 256, 256>>>(out);
}